// round 1
// baseline (speedup 1.0000x reference)
#include <cuda_runtime.h>

#define KNB 32
#define FC 64
#define CO 64
#define CIN 3
#define MAXN 20001
#define ROWP 68   // padded smem row stride (floats): conflict-free scalar + float4

// Precomputed per-source-point tables (L2-resident, ~5MB each)
__device__ float g_d[MAXN * FC];   // d[m,f] = -f_pad[m,f] - sum_i Wp2[f,i]*s_pad[m,i]
__device__ float g_R[MAXN * FC];   // R[m,o] = bn_r(f_pad[m] @ W_res^T)[o]
__device__ float g_c[MAXN * FC];   // c[n,f] = x_q[n,f] + sum_i Wp2[f,i]*(pos0[n,i]+q[n,i])

__device__ __forceinline__ float lrelu(float x) { return x >= 0.f ? x : 0.1f * x; }

__global__ void prep_kernel(
    const float* __restrict__ q, const float* __restrict__ s,
    const float* __restrict__ feat,
    const float* __restrict__ Wp2, const float* __restrict__ Wres,
    const float* __restrict__ bqg, const float* __restrict__ bqb,
    const float* __restrict__ bqm, const float* __restrict__ bqv,
    const float* __restrict__ bpg, const float* __restrict__ bpb,
    const float* __restrict__ bpm, const float* __restrict__ bpv,
    const float* __restrict__ brg, const float* __restrict__ brb,
    const float* __restrict__ brm, const float* __restrict__ brv,
    int NQ)
{
    int m = blockIdx.x;       // 0..NQ inclusive (NQ = shadow/zero row)
    int o = threadIdx.x;      // 64 threads = channel
    __shared__ float sf[FC];
    __shared__ float ss[4];
    bool real = m < NQ;
    if (real) {
        sf[o] = feat[m * FC + o];
        if (o < CIN) ss[o] = s[m * 3 + o];
    }
    __syncthreads();

    // R = bn_r(feat @ Wres^T); shadow row -> bn_r(0)
    float accR = 0.f;
    if (real) {
        const float4* w4 = (const float4*)(Wres + o * FC);
        #pragma unroll
        for (int f4 = 0; f4 < FC / 4; ++f4) {
            float4 w = w4[f4];
            accR += w.x * sf[f4*4+0] + w.y * sf[f4*4+1]
                  + w.z * sf[f4*4+2] + w.w * sf[f4*4+3];
        }
    }
    float sR = brg[o] * rsqrtf(brv[o] + 1e-5f);
    g_R[m * FC + o] = (accR - brm[o]) * sR + brb[o];

    float w0 = Wp2[o*3+0], w1 = Wp2[o*3+1], w2 = Wp2[o*3+2];

    // d (shadow row -> 0)
    float dd = 0.f;
    if (real) dd = -sf[o] - (w0 * ss[0] + w1 * ss[1] + w2 * ss[2]);
    g_d[m * FC + o] = dd;

    // c (query-side; only n < NQ used)
    if (real) {
        float xq = lrelu((sf[o] - bqm[o]) * (bqg[o] * rsqrtf(bqv[o] + 1e-5f)) + bqb[o]);
        float p0 = lrelu((ss[0] - bpm[0]) * (bpg[0] * rsqrtf(bpv[0] + 1e-5f)) + bpb[0]) + q[m*3+0];
        float p1 = lrelu((ss[1] - bpm[1]) * (bpg[1] * rsqrtf(bpv[1] + 1e-5f)) + bpb[1]) + q[m*3+1];
        float p2 = lrelu((ss[2] - bpm[2]) * (bpg[2] * rsqrtf(bpv[2] + 1e-5f)) + bpb[2]) + q[m*3+2];
        g_c[m * FC + o] = xq + w0 * p0 + w1 * p1 + w2 * p2;
    }
}

__global__ __launch_bounds__(256, 3) void main_kernel(
    const int*   __restrict__ inds,
    const float* __restrict__ s_points,
    const float* __restrict__ q_points,
    const float* __restrict__ Wattn,
    const float* __restrict__ b1g, const float* __restrict__ b1b,
    const float* __restrict__ b1m, const float* __restrict__ b1v,
    float* __restrict__ out, int NQ)
{
    extern __shared__ float sm[];
    float* Wa   = sm;                    // 192*64 = 12288
    float* at   = Wa + 192 * FC;         // 32*68
    float* Rg   = at + KNB * ROWP;       // 32*68
    float* xv   = Rg + KNB * ROWP;       // 32*4
    float* cs   = xv + KNB * 4;          // 64
    float* s1   = cs + FC;               // 64
    float* b1   = s1 + CO;               // 64
    int*   idxs = (int*)(b1 + CO);       // 32

    const int tid  = threadIdx.x;
    const int lane = tid & 31;
    const int warp = tid >> 5;

    // one-time CTA init: stage W_attn, bn1 affine
    for (int t = tid; t < (192 * FC) / 4; t += 256)
        ((float4*)Wa)[t] = ((const float4*)Wattn)[t];
    if (tid < CO) {
        float s = b1g[tid] * rsqrtf(b1v[tid] + 1e-5f);
        s1[tid] = s;
        b1[tid] = b1b[tid] - b1m[tid] * s;
    }
    __syncthreads();

    for (int p = blockIdx.x; p < NQ; p += gridDim.x) {
        // phase 0: indices, x_v, c row
        if (tid < KNB) {
            int idx = inds[p * KNB + tid];
            idxs[tid] = idx;
            bool v = idx < NQ;
            float qx = q_points[p*3+0], qy = q_points[p*3+1], qz = q_points[p*3+2];
            xv[tid*4+0] = (v ? s_points[idx*3+0] : 0.f) - qx;
            xv[tid*4+1] = (v ? s_points[idx*3+1] : 0.f) - qy;
            xv[tid*4+2] = (v ? s_points[idx*3+2] : 0.f) - qz;
        }
        if (tid < FC) cs[tid] = g_c[p * FC + tid];
        __syncthreads();

        // phase 1: gather d and R rows (256B each, L2-resident)
        for (int t = tid; t < KNB * 16; t += 256) {
            int k = t >> 4, j = t & 15;
            int idx = idxs[k];
            ((float4*)(at + k * ROWP))[j] = ((const float4*)(g_d + idx * FC))[j];
            ((float4*)(Rg + k * ROWP))[j] = ((const float4*)(g_R + idx * FC))[j];
        }
        __syncthreads();

        // phase 2: softmax over k per channel f (64 threads, conflict-free columns)
        if (tid < FC) {
            const float cf = cs[tid];
            float mx = -1e30f;
            #pragma unroll
            for (int k = 0; k < KNB; ++k) {
                float v = (at[k * ROWP + tid] + cf) * 0.125f;   // 1/sqrt(64)
                at[k * ROWP + tid] = v;
                mx = fmaxf(mx, v);
            }
            float sum = 0.f;
            #pragma unroll
            for (int k = 0; k < KNB; ++k) {
                float e = __expf(at[k * ROWP + tid] - mx);
                at[k * ROWP + tid] = e;
                sum += e;
            }
            float inv = 1.f / sum;
            #pragma unroll
            for (int k = 0; k < KNB; ++k) at[k * ROWP + tid] *= inv;
        }
        __syncthreads();

        // phase 3: attn @ W_attn^T contracted with x_v, + epilogue
        // lane = k; warp owns o in [warp*8, warp*8+8)
        const int o0 = warp * 8;
        float acc[8][3];
        #pragma unroll
        for (int oo = 0; oo < 8; ++oo)
            acc[oo][0] = acc[oo][1] = acc[oo][2] = 0.f;

        const float4* arow = (const float4*)(at + lane * ROWP);
        #pragma unroll 2
        for (int f4 = 0; f4 < 16; ++f4) {
            float4 a = arow[f4];
            #pragma unroll
            for (int oo = 0; oo < 8; ++oo) {
                const float* wp = Wa + (o0 + oo) * 3 * FC + f4 * 4;  // warp-uniform -> broadcast
                float4 w0 = *(const float4*)(wp);
                float4 w1 = *(const float4*)(wp + FC);
                float4 w2 = *(const float4*)(wp + 2 * FC);
                acc[oo][0] += a.x*w0.x + a.y*w0.y + a.z*w0.z + a.w*w0.w;
                acc[oo][1] += a.x*w1.x + a.y*w1.y + a.z*w1.z + a.w*w1.w;
                acc[oo][2] += a.x*w2.x + a.y*w2.y + a.z*w2.z + a.w*w2.w;
            }
        }

        float x0 = xv[lane*4+0], x1 = xv[lane*4+1], x2 = xv[lane*4+2];
        float4 r0 = ((const float4*)(Rg + lane * ROWP))[(o0 >> 2)];
        float4 r1 = ((const float4*)(Rg + lane * ROWP))[(o0 >> 2) + 1];
        float rr[8] = {r0.x, r0.y, r0.z, r0.w, r1.x, r1.y, r1.z, r1.w};

        #pragma unroll
        for (int oo = 0; oo < 8; ++oo) {
            int o = o0 + oo;
            float ye = acc[oo][0]*x0 + acc[oo][1]*x1 + acc[oo][2]*x2;
            ye = lrelu(ye * s1[o] + b1[o]);
            float y = lrelu(ye + rr[oo]);
            #pragma unroll
            for (int sh = 16; sh; sh >>= 1)
                y = fmaxf(y, __shfl_xor_sync(0xffffffffu, y, sh));
            if (lane == oo) out[p * CO + o] = y;
        }
        __syncthreads();   // protect smem before next point's phase 0
    }
}

extern "C" void kernel_launch(void* const* d_in, const int* in_sizes, int n_in,
                              void* d_out, int out_size)
{
    const float* q    = (const float*)d_in[0];
    const float* s    = (const float*)d_in[1];
    const int*   ind  = (const int*)  d_in[2];
    const float* feat = (const float*)d_in[3];
    const float* Wp2  = (const float*)d_in[4];
    const float* Wat  = (const float*)d_in[5];
    const float* Wre  = (const float*)d_in[6];
    const float* bqg  = (const float*)d_in[7];
    const float* bqb  = (const float*)d_in[8];
    const float* bqm  = (const float*)d_in[9];
    const float* bqv  = (const float*)d_in[10];
    const float* bpg  = (const float*)d_in[11];
    const float* bpb  = (const float*)d_in[12];
    const float* bpm  = (const float*)d_in[13];
    const float* bpv  = (const float*)d_in[14];
    const float* b1g  = (const float*)d_in[15];
    const float* b1b  = (const float*)d_in[16];
    const float* b1m  = (const float*)d_in[17];
    const float* b1v  = (const float*)d_in[18];
    const float* brg  = (const float*)d_in[19];
    const float* brb  = (const float*)d_in[20];
    const float* brm  = (const float*)d_in[21];
    const float* brv  = (const float*)d_in[22];

    int NQ = in_sizes[0] / 3;   // q_points is [Nq, 3]

    prep_kernel<<<NQ + 1, 64>>>(q, s, feat, Wp2, Wre,
                                bqg, bqb, bqm, bqv,
                                bpg, bpb, bpm, bpv,
                                brg, brb, brm, brv, NQ);

    const int smem_bytes = (192*FC + 2*KNB*ROWP + KNB*4 + FC + 2*CO + KNB) * 4;
    cudaFuncSetAttribute(main_kernel, cudaFuncAttributeMaxDynamicSharedMemorySize, smem_bytes);
    main_kernel<<<456, 256, smem_bytes>>>(ind, s, q, Wat,
                                          b1g, b1b, b1m, b1v,
                                          (float*)d_out, NQ);
}

// round 8
// speedup vs baseline: 2.0018x; 2.0018x over previous
#include <cuda_runtime.h>
#include <cstdint>

#define KNB 32
#define FC 64
#define CO 64
#define MAXN 20001

// Per-source-point tables (L2-resident, ~5MB each)
__device__ float g_E[MAXN * FC];   // E[m,f] = exp(0.125*(-f_pad[m,f] - sum_i Wp2[f,i]*s_pad[m,i]))
__device__ float g_R[MAXN * FC];   // R[m,o] = bn_r(f_pad[m] @ W_res^T)[o]

__device__ __forceinline__ float lrelu(float x) { return x >= 0.f ? x : 0.1f * x; }

__device__ __forceinline__ uint32_t cvt_tf32(float x) {
    uint32_t r;
    asm("cvt.rna.tf32.f32 %0, %1;" : "=r"(r) : "f"(x));
    return r;
}
__device__ __forceinline__ void mma_tf32(float* d, const uint32_t* a, const uint32_t* b) {
    asm volatile(
        "mma.sync.aligned.m16n8k8.row.col.f32.tf32.tf32.f32 "
        "{%0,%1,%2,%3}, {%4,%5,%6,%7}, {%8,%9}, {%0,%1,%2,%3};"
        : "+f"(d[0]), "+f"(d[1]), "+f"(d[2]), "+f"(d[3])
        : "r"(a[0]), "r"(a[1]), "r"(a[2]), "r"(a[3]), "r"(b[0]), "r"(b[1]));
}

// ---------------- prep kernel: build g_E / g_R ----------------
__global__ __launch_bounds__(256) void prep_kernel(
    const float* __restrict__ s,
    const float* __restrict__ feat,
    const float* __restrict__ Wp2, const float* __restrict__ Wres,
    const float* __restrict__ brg, const float* __restrict__ brb,
    const float* __restrict__ brm, const float* __restrict__ brv,
    int NQ)
{
    __shared__ float Ws[64 * 65];   // padded rows -> conflict-free column reads
    __shared__ float sf[4 * 68];    // 4 concurrent feat rows

    const int tid = threadIdx.x;
    const int o = tid & 63, sub = tid >> 6;

    for (int t = tid; t < 64 * 64; t += 256)
        Ws[(t >> 6) * 65 + (t & 63)] = Wres[t];

    const float sR = brg[o] * rsqrtf(brv[o] + 1e-5f);
    const float bR = brb[o] - brm[o] * sR;
    const float w0 = Wp2[o * 3 + 0], w1 = Wp2[o * 3 + 1], w2 = Wp2[o * 3 + 2];

    const int base = blockIdx.x * 32;
    for (int r = 0; r < 8; ++r) {
        const int m = base + r * 4 + sub;
        const bool real = (m < NQ);
        const bool any  = (m <= NQ);
        __syncthreads();
        sf[sub * 68 + o] = real ? feat[m * FC + o] : 0.f;
        __syncthreads();

        float accR = 0.f;
        if (real) {
            #pragma unroll
            for (int f = 0; f < FC; ++f)
                accR += Ws[o * 65 + f] * sf[sub * 68 + f];
        }
        float s0 = 0.f, s1v = 0.f, s2v = 0.f;
        if (real) { s0 = s[m * 3 + 0]; s1v = s[m * 3 + 1]; s2v = s[m * 3 + 2]; }
        if (any) {
            g_R[m * FC + o] = accR * sR + bR;
            float d = real ? (-sf[sub * 68 + o] - (w0 * s0 + w1 * s1v + w2 * s2v)) : 0.f;
            g_E[m * FC + o] = __expf(0.125f * d);
        }
    }
}

// ---------------- main kernel ----------------
// smem (floats):
#define AP_OFF    0        // A' tile [32][196] tf32 bits      (6272)
#define ESM_OFF   6272     // gathered E rows [32][68]         (2176)
#define RSM_OFF   8448     // gathered R rows [32][68]         (2176)
#define DRED_OFF  10624    // K-half partial D [32][68]        (2176)
#define INV_OFF   12800    // [64]
#define XV_OFF    12864    // [32][4]
#define S1_OFF    12992    // [64]
#define B1_OFF    13056    // [64]
#define PMAX_OFF  13120    // [2][64]
#define SMEM_FLOATS 13248
#define ASTR 196           // A' row stride (floats): conflict-free fragment reads

__global__ __launch_bounds__(512, 1) void main_kernel(
    const int*   __restrict__ inds,
    const float* __restrict__ s_points,
    const float* __restrict__ q_points,
    const float* __restrict__ Wattn,
    const float* __restrict__ b1g, const float* __restrict__ b1b,
    const float* __restrict__ b1m, const float* __restrict__ b1v,
    float* __restrict__ out, int NQ)
{
    extern __shared__ float sm[];
    const int tid  = threadIdx.x;
    const int lane = tid & 31;
    const int w    = tid >> 5;
    const int wm = w & 1;            // m-tile group: rows 16*wm
    const int wn = (w >> 1) & 3;     // n slab: cols 16*wn .. +15
    const int wk = w >> 3;           // K half: cc in [96*wk, 96*wk+96)

    const int qr = lane >> 2;        // quad row 0..7
    const int qc = lane & 3;         // 0..3

    // ---- one-time: B' fragments in registers (48 regs), bn1 affine ----
    uint32_t bf[12][2][2];
    #pragma unroll
    for (int kt = 0; kt < 12; ++kt) {
        #pragma unroll
        for (int nt = 0; nt < 2; ++nt) {
            int o = wn * 16 + nt * 8 + qr;
            #pragma unroll
            for (int h = 0; h < 2; ++h) {
                int cc = wk * 96 + kt * 8 + qc + 4 * h;
                // B'[cc][o] = Wattn[(o*3 + cc%3)*64 + cc/3]
                float v = Wattn[(o * 3 + (cc % 3)) * FC + (cc / 3)];
                bf[kt][nt][h] = cvt_tf32(v);
            }
        }
    }
    if (tid < CO) {
        float sc = b1g[tid] * rsqrtf(b1v[tid] + 1e-5f);
        sm[S1_OFF + tid] = sc;
        sm[B1_OFF + tid] = b1b[tid] - b1m[tid] * sc;
    }
    __syncthreads();

    for (int p = blockIdx.x; p < NQ; p += gridDim.x) {
        // ---- phase 1: gather E,R rows + xv ----
        {
            int k = tid >> 4, f4 = tid & 15;
            int idx = inds[p * KNB + k];          // 16 threads same addr -> broadcast
            float4 e4 = *(const float4*)(g_E + (size_t)idx * FC + f4 * 4);
            float4 r4 = *(const float4*)(g_R + (size_t)idx * FC + f4 * 4);
            *(float4*)(sm + ESM_OFF + k * 68 + f4 * 4) = e4;
            *(float4*)(sm + RSM_OFF + k * 68 + f4 * 4) = r4;
            if (tid < KNB) {
                int idx2 = inds[p * KNB + tid];   // FIX: per-k index for x_v (was tid>>4)
                bool v = idx2 < NQ;
                sm[XV_OFF + tid * 4 + 0] = (v ? s_points[idx2*3+0] : 0.f) - q_points[p*3+0];
                sm[XV_OFF + tid * 4 + 1] = (v ? s_points[idx2*3+1] : 0.f) - q_points[p*3+1];
                sm[XV_OFF + tid * 4 + 2] = (v ? s_points[idx2*3+2] : 0.f) - q_points[p*3+2];
            }
        }
        __syncthreads();

        // ---- phase 2: inv[f] = 1/sum_k E ----
        if (tid < FC) {
            float s = 0.f;
            #pragma unroll
            for (int k = 0; k < KNB; ++k) s += sm[ESM_OFF + k * 68 + tid];
            sm[INV_OFF + tid] = 1.f / s;
        }
        __syncthreads();

        // ---- phase 3: build A'[k][3f+i] = attn[k,f]*xv[k,i], tf32 ----
        {
            int k = tid >> 4;
            int f0 = (tid & 15) * 4;
            float x0 = sm[XV_OFF + k*4 + 0];
            float x1 = sm[XV_OFF + k*4 + 1];
            float x2 = sm[XV_OFF + k*4 + 2];
            float* Arow = sm + AP_OFF + k * ASTR;
            #pragma unroll
            for (int ff = 0; ff < 4; ++ff) {
                int f = f0 + ff;
                float a = sm[ESM_OFF + k * 68 + f] * sm[INV_OFF + f];
                Arow[3*f + 0] = __uint_as_float(cvt_tf32(a * x0));
                Arow[3*f + 1] = __uint_as_float(cvt_tf32(a * x1));
                Arow[3*f + 2] = __uint_as_float(cvt_tf32(a * x2));
            }
        }
        __syncthreads();

        // ---- phase 4: MMA [16 x 96] x [96 x 16] per warp ----
        float d[2][4];
        #pragma unroll
        for (int nt = 0; nt < 2; ++nt)
            #pragma unroll
            for (int j = 0; j < 4; ++j) d[nt][j] = 0.f;
        {
            const float* A = sm + AP_OFF + (wm * 16) * ASTR + wk * 96;
            #pragma unroll
            for (int kt = 0; kt < 12; ++kt) {
                const float* ab = A + qr * ASTR + kt * 8 + qc;
                uint32_t a[4];
                a[0] = __float_as_uint(ab[0]);
                a[1] = __float_as_uint(ab[8 * ASTR]);
                a[2] = __float_as_uint(ab[4]);
                a[3] = __float_as_uint(ab[8 * ASTR + 4]);
                mma_tf32(d[0], a, bf[kt][0]);
                mma_tf32(d[1], a, bf[kt][1]);
            }
        }

        // ---- phase 5: reduce the two K-halves ----
        if (wk == 1) {
            #pragma unroll
            for (int nt = 0; nt < 2; ++nt)
                #pragma unroll
                for (int j = 0; j < 4; ++j) {
                    int row = wm * 16 + qr + 8 * (j >> 1);
                    int col = wn * 16 + nt * 8 + 2 * qc + (j & 1);
                    sm[DRED_OFF + row * 68 + col] = d[nt][j];
                }
        }
        __syncthreads();

        // ---- phase 6: epilogue (kh0 warps): bn1, lrelu, +R, lrelu, max over k ----
        if (wk == 0) {
            float mx[2][2] = {{-1e30f, -1e30f}, {-1e30f, -1e30f}};
            #pragma unroll
            for (int nt = 0; nt < 2; ++nt)
                #pragma unroll
                for (int j = 0; j < 4; ++j) {
                    int row = wm * 16 + qr + 8 * (j >> 1);
                    int col = wn * 16 + nt * 8 + 2 * qc + (j & 1);
                    float ye = d[nt][j] + sm[DRED_OFF + row * 68 + col];
                    ye = lrelu(ye * sm[S1_OFF + col] + sm[B1_OFF + col]);
                    float y = lrelu(ye + sm[RSM_OFF + row * 68 + col]);
                    mx[nt][j & 1] = fmaxf(mx[nt][j & 1], y);
                }
            #pragma unroll
            for (int nt = 0; nt < 2; ++nt)
                #pragma unroll
                for (int par = 0; par < 2; ++par) {
                    float v = mx[nt][par];
                    v = fmaxf(v, __shfl_xor_sync(0xffffffffu, v, 4));
                    v = fmaxf(v, __shfl_xor_sync(0xffffffffu, v, 8));
                    v = fmaxf(v, __shfl_xor_sync(0xffffffffu, v, 16));
                    mx[nt][par] = v;
                }
            if (lane < 4) {
                #pragma unroll
                for (int nt = 0; nt < 2; ++nt)
                    #pragma unroll
                    for (int par = 0; par < 2; ++par) {
                        int col = wn * 16 + nt * 8 + 2 * lane + par;
                        sm[PMAX_OFF + wm * 64 + col] = mx[nt][par];
                    }
            }
        }
        __syncthreads();

        if (tid < CO)
            out[p * CO + tid] = fmaxf(sm[PMAX_OFF + tid], sm[PMAX_OFF + 64 + tid]);
        __syncthreads();   // protect smem before next point's gather
    }
}

extern "C" void kernel_launch(void* const* d_in, const int* in_sizes, int n_in,
                              void* d_out, int out_size)
{
    const float* q    = (const float*)d_in[0];
    const float* s    = (const float*)d_in[1];
    const int*   ind  = (const int*)  d_in[2];
    const float* feat = (const float*)d_in[3];
    const float* Wp2  = (const float*)d_in[4];
    const float* Wat  = (const float*)d_in[5];
    const float* Wre  = (const float*)d_in[6];
    const float* b1g  = (const float*)d_in[15];
    const float* b1b  = (const float*)d_in[16];
    const float* b1m  = (const float*)d_in[17];
    const float* b1v  = (const float*)d_in[18];
    const float* brg  = (const float*)d_in[19];
    const float* brb  = (const float*)d_in[20];
    const float* brm  = (const float*)d_in[21];
    const float* brv  = (const float*)d_in[22];

    int NQ = in_sizes[0] / 3;   // q_points is [Nq, 3]

    prep_kernel<<<(NQ + 1 + 31) / 32, 256>>>(s, feat, Wp2, Wre,
                                             brg, brb, brm, brv, NQ);

    const int smem_bytes = SMEM_FLOATS * 4;
    cudaFuncSetAttribute(main_kernel, cudaFuncAttributeMaxDynamicSharedMemorySize, smem_bytes);
    int grid = 148;
    if (grid > NQ) grid = NQ;
    main_kernel<<<grid, 512, smem_bytes>>>(ind, s, q, Wat,
                                           b1g, b1b, b1m, b1v,
                                           (float*)d_out, NQ);
}

// round 12
// speedup vs baseline: 2.5052x; 1.2515x over previous
#include <cuda_runtime.h>
#include <cstdint>

#define KNB 32
#define FC 64
#define CO 64
#define MAXN 20001

// Per-source-point tables (L2-resident, ~5MB each)
__device__ float g_E[MAXN * FC];   // E[m,f] = exp(0.125*(-f_pad[m,f] - sum_i Wp2[f,i]*s_pad[m,i]))
__device__ float g_R[MAXN * FC];   // R[m,o] = bn_r(f_pad[m] @ W_res^T)[o]

__device__ __forceinline__ float lrelu(float x) { return x >= 0.f ? x : 0.1f * x; }

__device__ __forceinline__ uint32_t cvt_tf32(float x) {
    uint32_t r;
    asm("cvt.rna.tf32.f32 %0, %1;" : "=r"(r) : "f"(x));
    return r;
}
__device__ __forceinline__ void mma_tf32(float* d, const uint32_t* a, const uint32_t* b) {
    asm volatile(
        "mma.sync.aligned.m16n8k8.row.col.f32.tf32.tf32.f32 "
        "{%0,%1,%2,%3}, {%4,%5,%6,%7}, {%8,%9}, {%0,%1,%2,%3};"
        : "+f"(d[0]), "+f"(d[1]), "+f"(d[2]), "+f"(d[3])
        : "r"(a[0]), "r"(a[1]), "r"(a[2]), "r"(a[3]), "r"(b[0]), "r"(b[1]));
}

// ---------------- prep kernel: build g_E / g_R ----------------
__global__ __launch_bounds__(256) void prep_kernel(
    const float* __restrict__ s,
    const float* __restrict__ feat,
    const float* __restrict__ Wp2, const float* __restrict__ Wres,
    const float* __restrict__ brg, const float* __restrict__ brb,
    const float* __restrict__ brm, const float* __restrict__ brv,
    int NQ)
{
    __shared__ float Ws[64 * 65];   // padded rows -> conflict-free column reads
    __shared__ float sf[4 * 68];    // 4 concurrent feat rows

    const int tid = threadIdx.x;
    const int o = tid & 63, sub = tid >> 6;

    for (int t = tid; t < 64 * 64; t += 256)
        Ws[(t >> 6) * 65 + (t & 63)] = Wres[t];

    const float sR = brg[o] * rsqrtf(brv[o] + 1e-5f);
    const float bR = brb[o] - brm[o] * sR;
    const float w0 = Wp2[o * 3 + 0], w1 = Wp2[o * 3 + 1], w2 = Wp2[o * 3 + 2];

    const int base = blockIdx.x * 32;
    for (int r = 0; r < 8; ++r) {
        const int m = base + r * 4 + sub;
        const bool real = (m < NQ);
        const bool any  = (m <= NQ);
        __syncthreads();
        sf[sub * 68 + o] = real ? feat[m * FC + o] : 0.f;
        __syncthreads();

        float accR = 0.f;
        if (real) {
            #pragma unroll
            for (int f = 0; f < FC; ++f)
                accR += Ws[o * 65 + f] * sf[sub * 68 + f];
        }
        float s0 = 0.f, s1v = 0.f, s2v = 0.f;
        if (real) { s0 = s[m * 3 + 0]; s1v = s[m * 3 + 1]; s2v = s[m * 3 + 2]; }
        if (any) {
            g_R[m * FC + o] = accR * sR + bR;
            float d = real ? (-sf[sub * 68 + o] - (w0 * s0 + w1 * s1v + w2 * s2v)) : 0.f;
            g_E[m * FC + o] = __expf(0.125f * d);
        }
    }
}

// ---------------- main kernel: 2 points (64 rows) per iteration ----------------
// smem (floats):
#define AP_OFF    0        // A' tile [64][196]                (12544)
#define ESM_OFF   12544    // gathered E rows [64][68]         (4352)
#define RSM_OFF   16896    // gathered R rows [64][68]         (4352)
#define DRED_OFF  21248    // K-half partial D [64][68]        (4352)
#define INV_OFF   25600    // [2][64]
#define XV_OFF    25728    // [64][4]
#define S1_OFF    25984    // [64]
#define B1_OFF    26048    // [64]
#define SMEM_FLOATS 26112
#define ASTR 196           // A' row stride (floats): conflict-free fragment reads

__global__ __launch_bounds__(512, 1) void main_kernel(
    const int*   __restrict__ inds,
    const float* __restrict__ s_points,
    const float* __restrict__ q_points,
    const float* __restrict__ Wattn,
    const float* __restrict__ b1g, const float* __restrict__ b1b,
    const float* __restrict__ b1m, const float* __restrict__ b1v,
    float* __restrict__ out, int NQ, int ntiles)
{
    extern __shared__ float sm[];
    const int tid  = threadIdx.x;
    const int lane = tid & 31;
    const int w    = tid >> 5;
    const int wk   = w >> 3;         // K half: cc in [96*wk, 96*wk+96)
    const int sub  = w & 7;
    const int wn   = sub & 3;        // n slab: cols 16*wn .. +15
    const int wm2  = sub >> 2;       // point/m-group: rows 32*wm2 .. +31

    const int qr = lane >> 2;        // quad row 0..7
    const int qc = lane & 3;         // 0..3

    // ---- one-time: B' fragments in registers (48 regs), bn1 affine ----
    uint32_t bf[12][2][2];
    #pragma unroll
    for (int kt = 0; kt < 12; ++kt) {
        #pragma unroll
        for (int nt = 0; nt < 2; ++nt) {
            int o = wn * 16 + nt * 8 + qr;
            #pragma unroll
            for (int h = 0; h < 2; ++h) {
                int cc = wk * 96 + kt * 8 + qc + 4 * h;
                // B'[cc][o] = Wattn[(o*3 + cc%3)*64 + cc/3]
                float v = Wattn[(o * 3 + (cc % 3)) * FC + (cc / 3)];
                bf[kt][nt][h] = cvt_tf32(v);
            }
        }
    }
    if (tid < CO) {
        float sc = b1g[tid] * rsqrtf(b1v[tid] + 1e-5f);
        sm[S1_OFF + tid] = sc;
        sm[B1_OFF + tid] = b1b[tid] - b1m[tid] * sc;
    }
    __syncthreads();

    for (int t = blockIdx.x; t < ntiles; t += gridDim.x) {
        const int p0 = t * 2;

        // ---- phase 1: gather E,R rows (64 rows x 16 float4) + xv ----
        #pragma unroll
        for (int rr = 0; rr < 2; ++rr) {
            int pair = tid + rr * 512;
            int row = pair >> 4, f4 = pair & 15;
            int pg = p0 + (row >> 5);
            int idx = (pg < NQ) ? inds[pg * KNB + (row & 31)] : NQ;  // broadcast x16
            float4 e4 = *(const float4*)(g_E + (size_t)idx * FC + f4 * 4);
            float4 r4 = *(const float4*)(g_R + (size_t)idx * FC + f4 * 4);
            *(float4*)(sm + ESM_OFF + row * 68 + f4 * 4) = e4;
            *(float4*)(sm + RSM_OFF + row * 68 + f4 * 4) = r4;
        }
        if (tid < 64) {
            int row = tid;
            int pg = p0 + (row >> 5);
            bool pv = pg < NQ;
            int idx2 = pv ? inds[pg * KNB + (row & 31)] : NQ;
            bool v = idx2 < NQ;
            float qx = pv ? q_points[pg*3+0] : 0.f;
            float qy = pv ? q_points[pg*3+1] : 0.f;
            float qz = pv ? q_points[pg*3+2] : 0.f;
            sm[XV_OFF + row * 4 + 0] = (v ? s_points[idx2*3+0] : 0.f) - qx;
            sm[XV_OFF + row * 4 + 1] = (v ? s_points[idx2*3+1] : 0.f) - qy;
            sm[XV_OFF + row * 4 + 2] = (v ? s_points[idx2*3+2] : 0.f) - qz;
        }
        __syncthreads();

        // ---- phase 2: inv[pt][f] = 1/sum_k E ----
        if (tid < 128) {
            int pt = tid >> 6, f = tid & 63;
            float s = 0.f;
            #pragma unroll
            for (int k = 0; k < KNB; ++k) s += sm[ESM_OFF + (pt * 32 + k) * 68 + f];
            sm[INV_OFF + tid] = 1.f / s;
        }
        __syncthreads();

        // ---- phase 3: build A'[row][3f+i] = attn[row,f]*xv[row,i], tf32 ----
        {
            int row = tid >> 3, seg = tid & 7;
            int pt = row >> 5;
            float x0 = sm[XV_OFF + row*4 + 0];
            float x1 = sm[XV_OFF + row*4 + 1];
            float x2 = sm[XV_OFF + row*4 + 2];
            float* Arow = sm + AP_OFF + row * ASTR;
            const float* Erow = sm + ESM_OFF + row * 68;
            const float* invp = sm + INV_OFF + pt * 64;
            #pragma unroll
            for (int ff = 0; ff < 8; ++ff) {
                int f = seg * 8 + ff;
                float a = Erow[f] * invp[f];
                Arow[3*f + 0] = __uint_as_float(cvt_tf32(a * x0));
                Arow[3*f + 1] = __uint_as_float(cvt_tf32(a * x1));
                Arow[3*f + 2] = __uint_as_float(cvt_tf32(a * x2));
            }
        }
        __syncthreads();

        // ---- phase 4: MMA — each warp [32 x 96] x [96 x 16] ----
        float d[2][2][4];                 // [mt][nt][j]
        #pragma unroll
        for (int mt = 0; mt < 2; ++mt)
            #pragma unroll
            for (int nt = 0; nt < 2; ++nt)
                #pragma unroll
                for (int j = 0; j < 4; ++j) d[mt][nt][j] = 0.f;
        {
            const float* A = sm + AP_OFF + (wm2 * 32) * ASTR + wk * 96;
            #pragma unroll
            for (int kt = 0; kt < 12; ++kt) {
                uint32_t a[2][4];
                #pragma unroll
                for (int mt = 0; mt < 2; ++mt) {
                    const float* ab = A + (mt * 16 + qr) * ASTR + kt * 8 + qc;
                    a[mt][0] = __float_as_uint(ab[0]);
                    a[mt][1] = __float_as_uint(ab[8 * ASTR]);
                    a[mt][2] = __float_as_uint(ab[4]);
                    a[mt][3] = __float_as_uint(ab[8 * ASTR + 4]);
                }
                #pragma unroll
                for (int mt = 0; mt < 2; ++mt) {
                    mma_tf32(d[mt][0], a[mt], bf[kt][0]);
                    mma_tf32(d[mt][1], a[mt], bf[kt][1]);
                }
            }
        }

        // ---- phase 5: K-half 1 writes partials ----
        if (wk == 1) {
            #pragma unroll
            for (int mt = 0; mt < 2; ++mt)
                #pragma unroll
                for (int nt = 0; nt < 2; ++nt)
                    #pragma unroll
                    for (int j = 0; j < 4; ++j) {
                        int row = wm2 * 32 + mt * 16 + qr + 8 * (j >> 1);
                        int col = wn * 16 + nt * 8 + 2 * qc + (j & 1);
                        sm[DRED_OFF + row * 68 + col] = d[mt][nt][j];
                    }
        }
        __syncthreads();

        // ---- phase 6: K-half 0 epilogue: bn1, lrelu, +R, lrelu, k-max, store ----
        if (wk == 0) {
            float mx[2][2] = {{-1e30f, -1e30f}, {-1e30f, -1e30f}};   // [nt][par]
            #pragma unroll
            for (int mt = 0; mt < 2; ++mt)
                #pragma unroll
                for (int nt = 0; nt < 2; ++nt)
                    #pragma unroll
                    for (int j = 0; j < 4; ++j) {
                        int row = wm2 * 32 + mt * 16 + qr + 8 * (j >> 1);
                        int col = wn * 16 + nt * 8 + 2 * qc + (j & 1);
                        float ye = d[mt][nt][j] + sm[DRED_OFF + row * 68 + col];
                        ye = lrelu(ye * sm[S1_OFF + col] + sm[B1_OFF + col]);
                        float y = lrelu(ye + sm[RSM_OFF + row * 68 + col]);
                        mx[nt][j & 1] = fmaxf(mx[nt][j & 1], y);
                    }
            // reduce over qr (rows) within warp; point = wm2, cols owned exclusively
            #pragma unroll
            for (int nt = 0; nt < 2; ++nt)
                #pragma unroll
                for (int par = 0; par < 2; ++par) {
                    float v = mx[nt][par];
                    v = fmaxf(v, __shfl_xor_sync(0xffffffffu, v, 4));
                    v = fmaxf(v, __shfl_xor_sync(0xffffffffu, v, 8));
                    v = fmaxf(v, __shfl_xor_sync(0xffffffffu, v, 16));
                    mx[nt][par] = v;
                }
            int p = p0 + wm2;
            if (lane < 4 && p < NQ) {
                #pragma unroll
                for (int nt = 0; nt < 2; ++nt)
                    #pragma unroll
                    for (int par = 0; par < 2; ++par) {
                        int col = wn * 16 + nt * 8 + 2 * lane + par;
                        out[p * CO + col] = mx[nt][par];
                    }
            }
        }
        __syncthreads();   // protect smem before next iteration's gather
    }
}

extern "C" void kernel_launch(void* const* d_in, const int* in_sizes, int n_in,
                              void* d_out, int out_size)
{
    const float* q    = (const float*)d_in[0];
    const float* s    = (const float*)d_in[1];
    const int*   ind  = (const int*)  d_in[2];
    const float* feat = (const float*)d_in[3];
    const float* Wp2  = (const float*)d_in[4];
    const float* Wat  = (const float*)d_in[5];
    const float* Wre  = (const float*)d_in[6];
    const float* b1g  = (const float*)d_in[15];
    const float* b1b  = (const float*)d_in[16];
    const float* b1m  = (const float*)d_in[17];
    const float* b1v  = (const float*)d_in[18];
    const float* brg  = (const float*)d_in[19];
    const float* brb  = (const float*)d_in[20];
    const float* brm  = (const float*)d_in[21];
    const float* brv  = (const float*)d_in[22];

    int NQ = in_sizes[0] / 3;   // q_points is [Nq, 3]
    int ntiles = (NQ + 1) / 2;

    prep_kernel<<<(NQ + 1 + 31) / 32, 256>>>(s, feat, Wp2, Wre,
                                             brg, brb, brm, brv, NQ);

    const int smem_bytes = SMEM_FLOATS * 4;
    cudaFuncSetAttribute(main_kernel, cudaFuncAttributeMaxDynamicSharedMemorySize, smem_bytes);
    int grid = 148;
    if (grid > ntiles) grid = ntiles;
    main_kernel<<<grid, 512, smem_bytes>>>(ind, s, q, Wat,
                                           b1g, b1b, b1m, b1v,
                                           (float*)d_out, NQ, ntiles);
}

// round 14
// speedup vs baseline: 2.6347x; 1.0517x over previous
#include <cuda_runtime.h>
#include <cstdint>

#define KNB 32
#define FC 64
#define CO 64
#define MAXN 20001

// Per-source-point tables (L2-resident, ~5MB each)
__device__ float g_E[MAXN * FC];   // E[m,f] = exp(0.125*(-f_pad[m,f] - sum_i Wp2[f,i]*s_pad[m,i]))
__device__ float g_R[MAXN * FC];   // R[m,o] = bn_r(f_pad[m] @ W_res^T)[o]

__device__ __forceinline__ float lrelu(float x) { return x >= 0.f ? x : 0.1f * x; }

__device__ __forceinline__ uint32_t cvt_tf32(float x) {
    uint32_t r;
    asm("cvt.rna.tf32.f32 %0, %1;" : "=r"(r) : "f"(x));
    return r;
}
__device__ __forceinline__ void mma_tf32(float* d, const uint32_t* a, const uint32_t* b) {
    asm volatile(
        "mma.sync.aligned.m16n8k8.row.col.f32.tf32.tf32.f32 "
        "{%0,%1,%2,%3}, {%4,%5,%6,%7}, {%8,%9}, {%0,%1,%2,%3};"
        : "+f"(d[0]), "+f"(d[1]), "+f"(d[2]), "+f"(d[3])
        : "r"(a[0]), "r"(a[1]), "r"(a[2]), "r"(a[3]), "r"(b[0]), "r"(b[1]));
}

// ---------------- prep kernel: build g_E / g_R ----------------
__global__ __launch_bounds__(256) void prep_kernel(
    const float* __restrict__ s,
    const float* __restrict__ feat,
    const float* __restrict__ Wp2, const float* __restrict__ Wres,
    const float* __restrict__ brg, const float* __restrict__ brb,
    const float* __restrict__ brm, const float* __restrict__ brv,
    int NQ)
{
    __shared__ float Ws[64 * 65];   // padded rows -> conflict-free column reads
    __shared__ float sf[4 * 68];    // 4 concurrent feat rows

    const int tid = threadIdx.x;
    const int o = tid & 63, sub = tid >> 6;

    for (int t = tid; t < 64 * 64; t += 256)
        Ws[(t >> 6) * 65 + (t & 63)] = Wres[t];

    const float sR = brg[o] * rsqrtf(brv[o] + 1e-5f);
    const float bR = brb[o] - brm[o] * sR;
    const float w0 = Wp2[o * 3 + 0], w1 = Wp2[o * 3 + 1], w2 = Wp2[o * 3 + 2];

    const int base = blockIdx.x * 32;
    for (int r = 0; r < 8; ++r) {
        const int m = base + r * 4 + sub;
        const bool real = (m < NQ);
        const bool any  = (m <= NQ);
        __syncthreads();
        sf[sub * 68 + o] = real ? feat[m * FC + o] : 0.f;
        __syncthreads();

        float accR = 0.f;
        if (real) {
            #pragma unroll
            for (int f = 0; f < FC; ++f)
                accR += Ws[o * 65 + f] * sf[sub * 68 + f];
        }
        float s0 = 0.f, s1v = 0.f, s2v = 0.f;
        if (real) { s0 = s[m * 3 + 0]; s1v = s[m * 3 + 1]; s2v = s[m * 3 + 2]; }
        if (any) {
            g_R[m * FC + o] = accR * sR + bR;
            float d = real ? (-sf[sub * 68 + o] - (w0 * s0 + w1 * s1v + w2 * s2v)) : 0.f;
            g_E[m * FC + o] = __expf(0.125f * d);
        }
    }
}

// ---------------- main kernel: 1 point per iter, 256 thr, 2 CTAs/SM ----------------
// smem (floats):
#define AP_OFF    0        // A' tile [32][196]                (6272)
#define ESM_OFF   6272     // gathered E rows [32][68]         (2176)
#define RSM_OFF   8448     // gathered R rows [32][68]         (2176)
#define DRED_OFF  10624    // K-half partial D [32][68]        (2176)
#define INV_OFF   12800    // [64]
#define XV_OFF    12864    // [32][4]
#define S1_OFF    12992    // [64]
#define B1_OFF    13056    // [64]
#define SMEM_FLOATS 13120
#define ASTR 196           // A' row stride (floats): conflict-free fragment reads

__global__ __launch_bounds__(256, 2) void main_kernel(
    const int*   __restrict__ inds,
    const float* __restrict__ s_points,
    const float* __restrict__ q_points,
    const float* __restrict__ Wattn,
    const float* __restrict__ b1g, const float* __restrict__ b1b,
    const float* __restrict__ b1m, const float* __restrict__ b1v,
    float* __restrict__ out, int NQ)
{
    extern __shared__ float sm[];
    const int tid  = threadIdx.x;
    const int lane = tid & 31;
    const int w    = tid >> 5;
    const int wk   = w >> 2;         // K half: cc in [96*wk, 96*wk+96)
    const int wn   = w & 3;          // n slab: cols 16*wn .. +15

    const int qr = lane >> 2;        // quad row 0..7
    const int qc = lane & 3;         // 0..3

    // ---- one-time: B' fragments in registers (48 regs), bn1 affine ----
    uint32_t bf[12][2][2];
    #pragma unroll
    for (int kt = 0; kt < 12; ++kt) {
        #pragma unroll
        for (int nt = 0; nt < 2; ++nt) {
            int o = wn * 16 + nt * 8 + qr;
            #pragma unroll
            for (int h = 0; h < 2; ++h) {
                int cc = wk * 96 + kt * 8 + qc + 4 * h;
                // B'[cc][o] = Wattn[(o*3 + cc%3)*64 + cc/3]
                float v = Wattn[(o * 3 + (cc % 3)) * FC + (cc / 3)];
                bf[kt][nt][h] = cvt_tf32(v);
            }
        }
    }
    if (tid < CO) {
        float sc = b1g[tid] * rsqrtf(b1v[tid] + 1e-5f);
        sm[S1_OFF + tid] = sc;
        sm[B1_OFF + tid] = b1b[tid] - b1m[tid] * sc;
    }
    __syncthreads();

    for (int p = blockIdx.x; p < NQ; p += gridDim.x) {
        // ---- phase 1: gather E,R rows (32 rows x 16 float4) + xv ----
        #pragma unroll
        for (int rr = 0; rr < 2; ++rr) {
            int pair = tid + rr * 256;
            int row = pair >> 4, f4 = pair & 15;
            int idx = inds[p * KNB + row];        // broadcast x16
            float4 e4 = *(const float4*)(g_E + (size_t)idx * FC + f4 * 4);
            float4 r4 = *(const float4*)(g_R + (size_t)idx * FC + f4 * 4);
            *(float4*)(sm + ESM_OFF + row * 68 + f4 * 4) = e4;
            *(float4*)(sm + RSM_OFF + row * 68 + f4 * 4) = r4;
        }
        if (tid < KNB) {
            int idx2 = inds[p * KNB + tid];
            bool v = idx2 < NQ;
            sm[XV_OFF + tid * 4 + 0] = (v ? s_points[idx2*3+0] : 0.f) - q_points[p*3+0];
            sm[XV_OFF + tid * 4 + 1] = (v ? s_points[idx2*3+1] : 0.f) - q_points[p*3+1];
            sm[XV_OFF + tid * 4 + 2] = (v ? s_points[idx2*3+2] : 0.f) - q_points[p*3+2];
        }
        __syncthreads();

        // ---- phase 2: inv[f] = 1/sum_k E  (256 threads: f=tid>>2, 8 rows each) ----
        {
            int f = tid >> 2, quarter = tid & 3;
            float s = 0.f;
            #pragma unroll
            for (int k = 0; k < 8; ++k)
                s += sm[ESM_OFF + (quarter * 8 + k) * 68 + f];
            s += __shfl_xor_sync(0xffffffffu, s, 1);
            s += __shfl_xor_sync(0xffffffffu, s, 2);
            if (quarter == 0) sm[INV_OFF + f] = 1.f / s;
        }
        __syncthreads();

        // ---- phase 3: build A'[row][3f+i] = attn[row,f]*xv[row,i], tf32 ----
        {
            int row = tid >> 3, seg = tid & 7;
            float x0 = sm[XV_OFF + row*4 + 0];
            float x1 = sm[XV_OFF + row*4 + 1];
            float x2 = sm[XV_OFF + row*4 + 2];
            float* Arow = sm + AP_OFF + row * ASTR;
            const float* Erow = sm + ESM_OFF + row * 68;
            const float* invp = sm + INV_OFF;
            #pragma unroll
            for (int ff = 0; ff < 8; ++ff) {
                int f = seg * 8 + ff;
                float a = Erow[f] * invp[f];
                Arow[3*f + 0] = __uint_as_float(cvt_tf32(a * x0));
                Arow[3*f + 1] = __uint_as_float(cvt_tf32(a * x1));
                Arow[3*f + 2] = __uint_as_float(cvt_tf32(a * x2));
            }
        }
        __syncthreads();

        // ---- phase 4: MMA — each warp [32 x 96] x [96 x 16] ----
        float d[2][2][4];                 // [mt][nt][j]
        #pragma unroll
        for (int mt = 0; mt < 2; ++mt)
            #pragma unroll
            for (int nt = 0; nt < 2; ++nt)
                #pragma unroll
                for (int j = 0; j < 4; ++j) d[mt][nt][j] = 0.f;
        {
            const float* A = sm + AP_OFF + wk * 96;
            #pragma unroll
            for (int kt = 0; kt < 12; ++kt) {
                uint32_t a[2][4];
                #pragma unroll
                for (int mt = 0; mt < 2; ++mt) {
                    const float* ab = A + (mt * 16 + qr) * ASTR + kt * 8 + qc;
                    a[mt][0] = __float_as_uint(ab[0]);
                    a[mt][1] = __float_as_uint(ab[8 * ASTR]);
                    a[mt][2] = __float_as_uint(ab[4]);
                    a[mt][3] = __float_as_uint(ab[8 * ASTR + 4]);
                }
                #pragma unroll
                for (int mt = 0; mt < 2; ++mt) {
                    mma_tf32(d[mt][0], a[mt], bf[kt][0]);
                    mma_tf32(d[mt][1], a[mt], bf[kt][1]);
                }
            }
        }

        // ---- phase 5: K-half 1 writes partials ----
        if (wk == 1) {
            #pragma unroll
            for (int mt = 0; mt < 2; ++mt)
                #pragma unroll
                for (int nt = 0; nt < 2; ++nt)
                    #pragma unroll
                    for (int j = 0; j < 4; ++j) {
                        int row = mt * 16 + qr + 8 * (j >> 1);
                        int col = wn * 16 + nt * 8 + 2 * qc + (j & 1);
                        sm[DRED_OFF + row * 68 + col] = d[mt][nt][j];
                    }
        }
        __syncthreads();

        // ---- phase 6: K-half 0 epilogue: bn1, lrelu, +R, lrelu, k-max, store ----
        if (wk == 0) {
            float mx[2][2] = {{-1e30f, -1e30f}, {-1e30f, -1e30f}};   // [nt][par]
            #pragma unroll
            for (int mt = 0; mt < 2; ++mt)
                #pragma unroll
                for (int nt = 0; nt < 2; ++nt)
                    #pragma unroll
                    for (int j = 0; j < 4; ++j) {
                        int row = mt * 16 + qr + 8 * (j >> 1);
                        int col = wn * 16 + nt * 8 + 2 * qc + (j & 1);
                        float ye = d[mt][nt][j] + sm[DRED_OFF + row * 68 + col];
                        ye = lrelu(ye * sm[S1_OFF + col] + sm[B1_OFF + col]);
                        float y = lrelu(ye + sm[RSM_OFF + row * 68 + col]);
                        mx[nt][j & 1] = fmaxf(mx[nt][j & 1], y);
                    }
            // reduce over rows (qr varies across lanes at stride 4); cols owned per (qc,par)
            #pragma unroll
            for (int nt = 0; nt < 2; ++nt)
                #pragma unroll
                for (int par = 0; par < 2; ++par) {
                    float v = mx[nt][par];
                    v = fmaxf(v, __shfl_xor_sync(0xffffffffu, v, 4));
                    v = fmaxf(v, __shfl_xor_sync(0xffffffffu, v, 8));
                    v = fmaxf(v, __shfl_xor_sync(0xffffffffu, v, 16));
                    mx[nt][par] = v;
                }
            if (lane < 4) {
                #pragma unroll
                for (int nt = 0; nt < 2; ++nt)
                    #pragma unroll
                    for (int par = 0; par < 2; ++par) {
                        int col = wn * 16 + nt * 8 + 2 * lane + par;
                        out[p * CO + col] = mx[nt][par];
                    }
            }
        }
        __syncthreads();   // protect smem before next iteration's gather
    }
}

extern "C" void kernel_launch(void* const* d_in, const int* in_sizes, int n_in,
                              void* d_out, int out_size)
{
    const float* q    = (const float*)d_in[0];
    const float* s    = (const float*)d_in[1];
    const int*   ind  = (const int*)  d_in[2];
    const float* feat = (const float*)d_in[3];
    const float* Wp2  = (const float*)d_in[4];
    const float* Wat  = (const float*)d_in[5];
    const float* Wre  = (const float*)d_in[6];
    const float* b1g  = (const float*)d_in[15];
    const float* b1b  = (const float*)d_in[16];
    const float* b1m  = (const float*)d_in[17];
    const float* b1v  = (const float*)d_in[18];
    const float* brg  = (const float*)d_in[19];
    const float* brb  = (const float*)d_in[20];
    const float* brm  = (const float*)d_in[21];
    const float* brv  = (const float*)d_in[22];

    int NQ = in_sizes[0] / 3;   // q_points is [Nq, 3]

    prep_kernel<<<(NQ + 1 + 31) / 32, 256>>>(s, feat, Wp2, Wre,
                                             brg, brb, brm, brv, NQ);

    const int smem_bytes = SMEM_FLOATS * 4;
    cudaFuncSetAttribute(main_kernel, cudaFuncAttributeMaxDynamicSharedMemorySize, smem_bytes);
    int grid = 296;
    if (grid > NQ) grid = NQ;
    main_kernel<<<grid, 256, smem_bytes>>>(ind, s, q, Wat,
                                           b1g, b1b, b1m, b1v,
                                           (float*)d_out, NQ);
}

// round 15
// speedup vs baseline: 2.6997x; 1.0246x over previous
#include <cuda_runtime.h>
#include <cstdint>

#define KNB 32
#define FC 64
#define CO 64
#define MAXN 20001

// Per-source-point tables (L2-resident, ~5MB each)
__device__ float g_E[MAXN * FC];   // E[m,f] = exp(0.125*(-f_pad[m,f] - sum_i Wp2[f,i]*s_pad[m,i]))
__device__ float g_R[MAXN * FC];   // R[m,o] = bn_r(f_pad[m] @ W_res^T)[o]

__device__ __forceinline__ float lrelu(float x) { return x >= 0.f ? x : 0.1f * x; }

__device__ __forceinline__ uint32_t cvt_tf32(float x) {
    uint32_t r;
    asm("cvt.rna.tf32.f32 %0, %1;" : "=r"(r) : "f"(x));
    return r;
}
__device__ __forceinline__ void mma_tf32(float* d, const uint32_t* a, const uint32_t* b) {
    asm volatile(
        "mma.sync.aligned.m16n8k8.row.col.f32.tf32.tf32.f32 "
        "{%0,%1,%2,%3}, {%4,%5,%6,%7}, {%8,%9}, {%0,%1,%2,%3};"
        : "+f"(d[0]), "+f"(d[1]), "+f"(d[2]), "+f"(d[3])
        : "r"(a[0]), "r"(a[1]), "r"(a[2]), "r"(a[3]), "r"(b[0]), "r"(b[1]));
}
__device__ __forceinline__ uint32_t smem_u32(const void* p) {
    uint32_t a;
    asm("{ .reg .u64 t; cvta.to.shared.u64 t, %1; cvt.u32.u64 %0, t; }" : "=r"(a) : "l"(p));
    return a;
}
__device__ __forceinline__ void cp16(uint32_t dst, const float* src) {
    asm volatile("cp.async.cg.shared.global [%0], [%1], 16;" :: "r"(dst), "l"(src));
}
__device__ __forceinline__ void cp4(uint32_t dst, const float* src, int srcsize) {
    asm volatile("cp.async.ca.shared.global [%0], [%1], 4, %2;" :: "r"(dst), "l"(src), "r"(srcsize));
}
__device__ __forceinline__ void cp_commit() { asm volatile("cp.async.commit_group;" ::: "memory"); }
__device__ __forceinline__ void cp_wait0()  { asm volatile("cp.async.wait_group 0;"  ::: "memory"); }

// ---------------- prep kernel: build g_E / g_R ----------------
__global__ __launch_bounds__(256) void prep_kernel(
    const float* __restrict__ s,
    const float* __restrict__ feat,
    const float* __restrict__ Wp2, const float* __restrict__ Wres,
    const float* __restrict__ brg, const float* __restrict__ brb,
    const float* __restrict__ brm, const float* __restrict__ brv,
    int NQ)
{
    __shared__ float Ws[64 * 65];
    __shared__ float sf[4 * 68];

    const int tid = threadIdx.x;
    const int o = tid & 63, sub = tid >> 6;

    for (int t = tid; t < 64 * 64; t += 256)
        Ws[(t >> 6) * 65 + (t & 63)] = Wres[t];

    const float sR = brg[o] * rsqrtf(brv[o] + 1e-5f);
    const float bR = brb[o] - brm[o] * sR;
    const float w0 = Wp2[o * 3 + 0], w1 = Wp2[o * 3 + 1], w2 = Wp2[o * 3 + 2];

    const int base = blockIdx.x * 32;
    for (int r = 0; r < 8; ++r) {
        const int m = base + r * 4 + sub;
        const bool real = (m < NQ);
        const bool any  = (m <= NQ);
        __syncthreads();
        sf[sub * 68 + o] = real ? feat[m * FC + o] : 0.f;
        __syncthreads();

        float accR = 0.f;
        if (real) {
            #pragma unroll
            for (int f = 0; f < FC; ++f)
                accR += Ws[o * 65 + f] * sf[sub * 68 + f];
        }
        float s0 = 0.f, s1v = 0.f, s2v = 0.f;
        if (real) { s0 = s[m * 3 + 0]; s1v = s[m * 3 + 1]; s2v = s[m * 3 + 2]; }
        if (any) {
            g_R[m * FC + o] = accR * sR + bR;
            float d = real ? (-sf[sub * 68 + o] - (w0 * s0 + w1 * s1v + w2 * s2v)) : 0.f;
            g_E[m * FC + o] = __expf(0.125f * d);
        }
    }
}

// ---------------- main kernel: cp.async double-buffered pipeline ----------------
// smem layout (floats):
#define AP_OFF    0        // A' tile [32][196]                (6272)
#define ESM_OFF   6272     // E rows  [2][32][68]              (4352)
#define RSM_OFF   10624    // R rows  [2][32][68]              (4352)
#define DRED_OFF  14976    // K-half partial D [32][68]        (2176)
#define INV_OFF   17152    // [64]
#define SPQ_OFF   17216    // [2][132]: 32x4 raw sp + 4 q      (264)
#define S1_OFF    17480    // [64]
#define B1_OFF    17544    // [64]
#define SMEM_FLOATS 17608
#define ASTR 196

__global__ __launch_bounds__(256, 2) void main_kernel(
    const int*   __restrict__ inds,
    const float* __restrict__ s_points,
    const float* __restrict__ q_points,
    const float* __restrict__ Wattn,
    const float* __restrict__ b1g, const float* __restrict__ b1b,
    const float* __restrict__ b1m, const float* __restrict__ b1v,
    float* __restrict__ out, int NQ)
{
    extern __shared__ float sm[];
    const uint32_t sb = smem_u32(sm);
    const int tid  = threadIdx.x;
    const int lane = tid & 31;
    const int w    = tid >> 5;
    const int wk   = w >> 2;         // K half
    const int wn   = w & 3;          // n slab

    const int qr = lane >> 2;
    const int qc = lane & 3;

    const int rowA = tid >> 4;       // E/R prefetch rows (0..15, +16)
    const int f4   = tid & 15;
    const int rowC = tid >> 2;       // sp prefetch row
    const int cC   = tid & 3;

    // ---- one-time: B' fragments in registers, bn1 affine ----
    uint32_t bf[12][2][2];
    #pragma unroll
    for (int kt = 0; kt < 12; ++kt) {
        #pragma unroll
        for (int nt = 0; nt < 2; ++nt) {
            int o = wn * 16 + nt * 8 + qr;
            #pragma unroll
            for (int h = 0; h < 2; ++h) {
                int cc = wk * 96 + kt * 8 + qc + 4 * h;
                float v = Wattn[(o * 3 + (cc % 3)) * FC + (cc / 3)];
                bf[kt][nt][h] = cvt_tf32(v);
            }
        }
    }
    if (tid < CO) {
        float sc = b1g[tid] * rsqrtf(b1v[tid] + 1e-5f);
        sm[S1_OFF + tid] = sc;
        sm[B1_OFF + tid] = b1b[tid] - b1m[tid] * sc;
    }

    const int stride = gridDim.x;

    // ---- prologue: prefetch first point into buffer 0 ----
    {
        int p0 = blockIdx.x;
        if (p0 < NQ) {
            int iA = inds[p0 * KNB + rowA];
            int iB = inds[p0 * KNB + 16 + rowA];
            uint32_t eb = sb + (ESM_OFF) * 4;
            uint32_t rb = sb + (RSM_OFF) * 4;
            cp16(eb + (rowA * 68 + f4 * 4) * 4,        g_E + (size_t)iA * FC + f4 * 4);
            cp16(rb + (rowA * 68 + f4 * 4) * 4,        g_R + (size_t)iA * FC + f4 * 4);
            cp16(eb + ((16 + rowA) * 68 + f4 * 4) * 4, g_E + (size_t)iB * FC + f4 * 4);
            cp16(rb + ((16 + rowA) * 68 + f4 * 4) * 4, g_R + (size_t)iB * FC + f4 * 4);
            if (tid < 128 && cC < 3) {
                int iC = inds[p0 * KNB + rowC];
                cp4(sb + (SPQ_OFF + rowC * 4 + cC) * 4, s_points + (size_t)iC * 3 + cC,
                    (iC < NQ) ? 4 : 0);
            }
            if (tid < 3)
                cp4(sb + (SPQ_OFF + 128 + tid) * 4, q_points + (size_t)p0 * 3 + tid, 4);
        }
        cp_commit();
    }
    __syncthreads();

    int buf = 0;
    for (int p = blockIdx.x; p < NQ; p += stride) {
        const int pn = p + stride;
        const bool hn = pn < NQ;

        // early index loads for next point (latency hides under phases 2-3)
        int iA = 0, iB = 0, iC = 0;
        if (hn) {
            iA = inds[pn * KNB + rowA];
            iB = inds[pn * KNB + 16 + rowA];
            if (tid < 128 && cC < 3) iC = inds[pn * KNB + rowC];
        }

        cp_wait0();
        __syncthreads();     // buffer 'buf' ready for all threads

        const int EB = ESM_OFF + buf * 2176;
        const int RB = RSM_OFF + buf * 2176;
        const int SQ = SPQ_OFF + buf * 132;

        // ---- phase 2: inv[f] = 1/sum_k E ----
        {
            int f = tid >> 2, quarter = tid & 3;
            float s = 0.f;
            #pragma unroll
            for (int k = 0; k < 8; ++k)
                s += sm[EB + (quarter * 8 + k) * 68 + f];
            s += __shfl_xor_sync(0xffffffffu, s, 1);
            s += __shfl_xor_sync(0xffffffffu, s, 2);
            if (quarter == 0) sm[INV_OFF + f] = 1.f / s;
        }
        __syncthreads();

        // ---- phase 3: build A'[row][3f+i] = attn[row,f]*xv[row,i], tf32 ----
        {
            int row = tid >> 3, seg = tid & 7;
            float x0 = sm[SQ + row * 4 + 0] - sm[SQ + 128 + 0];
            float x1 = sm[SQ + row * 4 + 1] - sm[SQ + 128 + 1];
            float x2 = sm[SQ + row * 4 + 2] - sm[SQ + 128 + 2];
            float* Arow = sm + AP_OFF + row * ASTR;
            const float* Erow = sm + EB + row * 68;
            const float* invp = sm + INV_OFF;
            #pragma unroll
            for (int ff = 0; ff < 8; ++ff) {
                int f = seg * 8 + ff;
                float a = Erow[f] * invp[f];
                Arow[3*f + 0] = __uint_as_float(cvt_tf32(a * x0));
                Arow[3*f + 1] = __uint_as_float(cvt_tf32(a * x1));
                Arow[3*f + 2] = __uint_as_float(cvt_tf32(a * x2));
            }
        }
        __syncthreads();

        // ---- issue prefetch for next point into buf^1 (hidden under MMA+epilogue) ----
        if (hn) {
            uint32_t eb = sb + (ESM_OFF + (buf ^ 1) * 2176) * 4;
            uint32_t rb = sb + (RSM_OFF + (buf ^ 1) * 2176) * 4;
            uint32_t sq = sb + (SPQ_OFF + (buf ^ 1) * 132) * 4;
            cp16(eb + (rowA * 68 + f4 * 4) * 4,        g_E + (size_t)iA * FC + f4 * 4);
            cp16(rb + (rowA * 68 + f4 * 4) * 4,        g_R + (size_t)iA * FC + f4 * 4);
            cp16(eb + ((16 + rowA) * 68 + f4 * 4) * 4, g_E + (size_t)iB * FC + f4 * 4);
            cp16(rb + ((16 + rowA) * 68 + f4 * 4) * 4, g_R + (size_t)iB * FC + f4 * 4);
            if (tid < 128 && cC < 3)
                cp4(sq + (rowC * 4 + cC) * 4, s_points + (size_t)iC * 3 + cC,
                    (iC < NQ) ? 4 : 0);
            if (tid < 3)
                cp4(sq + (128 + tid) * 4, q_points + (size_t)pn * 3 + tid, 4);
        }
        cp_commit();

        // ---- phase 4: MMA — each warp [32 x 96] x [96 x 16] ----
        float d[2][2][4];
        #pragma unroll
        for (int mt = 0; mt < 2; ++mt)
            #pragma unroll
            for (int nt = 0; nt < 2; ++nt)
                #pragma unroll
                for (int j = 0; j < 4; ++j) d[mt][nt][j] = 0.f;
        {
            const float* A = sm + AP_OFF + wk * 96;
            #pragma unroll
            for (int kt = 0; kt < 12; ++kt) {
                uint32_t a[2][4];
                #pragma unroll
                for (int mt = 0; mt < 2; ++mt) {
                    const float* ab = A + (mt * 16 + qr) * ASTR + kt * 8 + qc;
                    a[mt][0] = __float_as_uint(ab[0]);
                    a[mt][1] = __float_as_uint(ab[8 * ASTR]);
                    a[mt][2] = __float_as_uint(ab[4]);
                    a[mt][3] = __float_as_uint(ab[8 * ASTR + 4]);
                }
                #pragma unroll
                for (int mt = 0; mt < 2; ++mt) {
                    mma_tf32(d[mt][0], a[mt], bf[kt][0]);
                    mma_tf32(d[mt][1], a[mt], bf[kt][1]);
                }
            }
        }

        // ---- phase 5: K-half 1 writes partials ----
        if (wk == 1) {
            #pragma unroll
            for (int mt = 0; mt < 2; ++mt)
                #pragma unroll
                for (int nt = 0; nt < 2; ++nt)
                    #pragma unroll
                    for (int j = 0; j < 4; ++j) {
                        int row = mt * 16 + qr + 8 * (j >> 1);
                        int col = wn * 16 + nt * 8 + 2 * qc + (j & 1);
                        sm[DRED_OFF + row * 68 + col] = d[mt][nt][j];
                    }
        }
        __syncthreads();

        // ---- phase 6: K-half 0 epilogue: bn1, lrelu, +R, lrelu, k-max, store ----
        if (wk == 0) {
            float mx[2][2] = {{-1e30f, -1e30f}, {-1e30f, -1e30f}};
            #pragma unroll
            for (int mt = 0; mt < 2; ++mt)
                #pragma unroll
                for (int nt = 0; nt < 2; ++nt)
                    #pragma unroll
                    for (int j = 0; j < 4; ++j) {
                        int row = mt * 16 + qr + 8 * (j >> 1);
                        int col = wn * 16 + nt * 8 + 2 * qc + (j & 1);
                        float ye = d[mt][nt][j] + sm[DRED_OFF + row * 68 + col];
                        ye = lrelu(ye * sm[S1_OFF + col] + sm[B1_OFF + col]);
                        float y = lrelu(ye + sm[RB + row * 68 + col]);
                        mx[nt][j & 1] = fmaxf(mx[nt][j & 1], y);
                    }
            #pragma unroll
            for (int nt = 0; nt < 2; ++nt)
                #pragma unroll
                for (int par = 0; par < 2; ++par) {
                    float v = mx[nt][par];
                    v = fmaxf(v, __shfl_xor_sync(0xffffffffu, v, 4));
                    v = fmaxf(v, __shfl_xor_sync(0xffffffffu, v, 8));
                    v = fmaxf(v, __shfl_xor_sync(0xffffffffu, v, 16));
                    mx[nt][par] = v;
                }
            if (lane < 4) {
                #pragma unroll
                for (int nt = 0; nt < 2; ++nt)
                    #pragma unroll
                    for (int par = 0; par < 2; ++par) {
                        int col = wn * 16 + nt * 8 + 2 * lane + par;
                        out[p * CO + col] = mx[nt][par];
                    }
            }
        }
        // no trailing sync: next iteration's cp_wait0 + __syncthreads covers
        // AP (rewritten 2 syncs later) and DRED (3 syncs later)
        buf ^= 1;
    }
}

extern "C" void kernel_launch(void* const* d_in, const int* in_sizes, int n_in,
                              void* d_out, int out_size)
{
    const float* q    = (const float*)d_in[0];
    const float* s    = (const float*)d_in[1];
    const int*   ind  = (const int*)  d_in[2];
    const float* feat = (const float*)d_in[3];
    const float* Wp2  = (const float*)d_in[4];
    const float* Wat  = (const float*)d_in[5];
    const float* Wre  = (const float*)d_in[6];
    const float* b1g  = (const float*)d_in[15];
    const float* b1b  = (const float*)d_in[16];
    const float* b1m  = (const float*)d_in[17];
    const float* b1v  = (const float*)d_in[18];
    const float* brg  = (const float*)d_in[19];
    const float* brb  = (const float*)d_in[20];
    const float* brm  = (const float*)d_in[21];
    const float* brv  = (const float*)d_in[22];

    int NQ = in_sizes[0] / 3;

    prep_kernel<<<(NQ + 1 + 31) / 32, 256>>>(s, feat, Wp2, Wre,
                                             brg, brb, brm, brv, NQ);

    const int smem_bytes = SMEM_FLOATS * 4;
    cudaFuncSetAttribute(main_kernel, cudaFuncAttributeMaxDynamicSharedMemorySize, smem_bytes);
    int grid = 296;
    if (grid > NQ) grid = NQ;
    main_kernel<<<grid, 256, smem_bytes>>>(ind, s, q, Wat,
                                           b1g, b1b, b1m, b1v,
                                           (float*)d_out, NQ);
}

// round 16
// speedup vs baseline: 2.9224x; 1.0825x over previous
#include <cuda_runtime.h>
#include <cuda_fp16.h>
#include <cstdint>

#define KNB 32
#define FC 64
#define CO 64
#define MAXN 20001

__device__ float g_E[MAXN * FC];   // E[m,f] = exp(0.125*(-f_pad[m,f] - sum_i Wp2[f,i]*s_pad[m,i]))
__device__ float g_R[MAXN * FC];   // R[m,o] = bn_r(f_pad[m] @ W_res^T)[o]

__device__ __forceinline__ float lrelu(float x) { return x >= 0.f ? x : 0.1f * x; }

__device__ __forceinline__ uint32_t pack_h2(float lo, float hi) {
    __half2 h = __floats2half2_rn(lo, hi);
    return *reinterpret_cast<uint32_t*>(&h);
}
__device__ __forceinline__ void mma_f16(float* d, const uint32_t* a, const uint32_t* b) {
    asm volatile(
        "mma.sync.aligned.m16n8k16.row.col.f32.f16.f16.f32 "
        "{%0,%1,%2,%3}, {%4,%5,%6,%7}, {%8,%9}, {%0,%1,%2,%3};"
        : "+f"(d[0]), "+f"(d[1]), "+f"(d[2]), "+f"(d[3])
        : "r"(a[0]), "r"(a[1]), "r"(a[2]), "r"(a[3]), "r"(b[0]), "r"(b[1]));
}
__device__ __forceinline__ uint32_t smem_u32(const void* p) {
    uint32_t a;
    asm("{ .reg .u64 t; cvta.to.shared.u64 t, %1; cvt.u32.u64 %0, t; }" : "=r"(a) : "l"(p));
    return a;
}
__device__ __forceinline__ void cp16(uint32_t dst, const float* src) {
    asm volatile("cp.async.cg.shared.global [%0], [%1], 16;" :: "r"(dst), "l"(src));
}
__device__ __forceinline__ void cp4(uint32_t dst, const float* src, int srcsize) {
    asm volatile("cp.async.ca.shared.global [%0], [%1], 4, %2;" :: "r"(dst), "l"(src), "r"(srcsize));
}
__device__ __forceinline__ void cp_commit() { asm volatile("cp.async.commit_group;" ::: "memory"); }
__device__ __forceinline__ void cp_wait0()  { asm volatile("cp.async.wait_group 0;"  ::: "memory"); }

// ---------------- prep kernel: build g_E / g_R ----------------
__global__ __launch_bounds__(256) void prep_kernel(
    const float* __restrict__ s,
    const float* __restrict__ feat,
    const float* __restrict__ Wp2, const float* __restrict__ Wres,
    const float* __restrict__ brg, const float* __restrict__ brb,
    const float* __restrict__ brm, const float* __restrict__ brv,
    int NQ)
{
    __shared__ float Ws[64 * 65];
    __shared__ float sf[4 * 68];

    const int tid = threadIdx.x;
    const int o = tid & 63, sub = tid >> 6;

    for (int t = tid; t < 64 * 64; t += 256)
        Ws[(t >> 6) * 65 + (t & 63)] = Wres[t];

    const float sR = brg[o] * rsqrtf(brv[o] + 1e-5f);
    const float bR = brb[o] - brm[o] * sR;
    const float w0 = Wp2[o * 3 + 0], w1 = Wp2[o * 3 + 1], w2 = Wp2[o * 3 + 2];

    const int base = blockIdx.x * 32;
    for (int r = 0; r < 8; ++r) {
        const int m = base + r * 4 + sub;
        const bool real = (m < NQ);
        const bool any  = (m <= NQ);
        __syncthreads();
        sf[sub * 68 + o] = real ? feat[m * FC + o] : 0.f;
        __syncthreads();

        float accR = 0.f;
        if (real) {
            #pragma unroll
            for (int f = 0; f < FC; ++f)
                accR += Ws[o * 65 + f] * sf[sub * 68 + f];
        }
        float s0 = 0.f, s1v = 0.f, s2v = 0.f;
        if (real) { s0 = s[m * 3 + 0]; s1v = s[m * 3 + 1]; s2v = s[m * 3 + 2]; }
        if (any) {
            g_R[m * FC + o] = accR * sR + bR;
            float d = real ? (-sf[sub * 68 + o] - (w0 * s0 + w1 * s1v + w2 * s2v)) : 0.f;
            g_E[m * FC + o] = __expf(0.125f * d);
        }
    }
}

// ---------------- main kernel: fp16 MMA, full-K per warp, 3 syncs/point ----------------
// smem layout (float units):
#define AH_W    101       // A' row stride in 32-bit words (202 halves)
#define AP_OFF  0         // A' [32 rows][101 words] as half2     (3232)
#define ESM_OFF 3232      // E rows [2][32][68]                    (4352)
#define RSM_OFF 7584      // R rows [2][32][68]                    (4352)
#define INV_OFF 11936     // [64]
#define SPQ_OFF 12000     // [2][132]: 32x4 raw sp + 4 q           (264)
#define S1_OFF  12264     // [64]
#define B1_OFF  12328     // [64]
#define SMEM_FLOATS 12392

__global__ __launch_bounds__(256, 2) void main_kernel(
    const int*   __restrict__ inds,
    const float* __restrict__ s_points,
    const float* __restrict__ q_points,
    const float* __restrict__ Wattn,
    const float* __restrict__ b1g, const float* __restrict__ b1b,
    const float* __restrict__ b1m, const float* __restrict__ b1v,
    float* __restrict__ out, int NQ)
{
    extern __shared__ float sm[];
    uint32_t* smw = reinterpret_cast<uint32_t*>(sm);
    const uint32_t sb = smem_u32(sm);
    const int tid  = threadIdx.x;
    const int lane = tid & 31;
    const int w    = tid >> 5;          // warp = n-slab: cols [8w, 8w+8)

    const int qr = lane >> 2;           // group id 0..7
    const int qc = lane & 3;            // thread-in-group

    const int rowA = tid >> 4;          // E/R prefetch rows (0..15, +16)
    const int f4   = tid & 15;
    const int rowC = tid >> 2;          // sp prefetch row
    const int cC   = tid & 3;

    // ---- one-time: B' half2 fragments (24 regs), bn1 affine ----
    // B'[cc][o] = Wattn[(o*3 + cc%3)*64 + cc/3],  o = 8w + qr
    uint32_t bf[12][2];
    {
        const int o = 8 * w + qr;
        #pragma unroll
        for (int kt = 0; kt < 12; ++kt) {
            #pragma unroll
            for (int r = 0; r < 2; ++r) {
                int cc0 = kt * 16 + 8 * r + 2 * qc;
                float v0 = Wattn[(o * 3 + (cc0 % 3)) * FC + (cc0 / 3)];
                int cc1 = cc0 + 1;
                float v1 = Wattn[(o * 3 + (cc1 % 3)) * FC + (cc1 / 3)];
                bf[kt][r] = pack_h2(v0, v1);
            }
        }
    }
    if (tid < CO) {
        float sc = b1g[tid] * rsqrtf(b1v[tid] + 1e-5f);
        sm[S1_OFF + tid] = sc;
        sm[B1_OFF + tid] = b1b[tid] - b1m[tid] * sc;
    }

    const int stride = gridDim.x;

    // ---- prologue: prefetch first point into buffer 0 ----
    {
        int p0 = blockIdx.x;
        if (p0 < NQ) {
            int iA = inds[p0 * KNB + rowA];
            int iB = inds[p0 * KNB + 16 + rowA];
            uint32_t eb = sb + (ESM_OFF) * 4;
            uint32_t rb = sb + (RSM_OFF) * 4;
            cp16(eb + (rowA * 68 + f4 * 4) * 4,        g_E + (size_t)iA * FC + f4 * 4);
            cp16(rb + (rowA * 68 + f4 * 4) * 4,        g_R + (size_t)iA * FC + f4 * 4);
            cp16(eb + ((16 + rowA) * 68 + f4 * 4) * 4, g_E + (size_t)iB * FC + f4 * 4);
            cp16(rb + ((16 + rowA) * 68 + f4 * 4) * 4, g_R + (size_t)iB * FC + f4 * 4);
            if (tid < 128 && cC < 3) {
                int iC = inds[p0 * KNB + rowC];
                cp4(sb + (SPQ_OFF + rowC * 4 + cC) * 4, s_points + (size_t)iC * 3 + cC,
                    (iC < NQ) ? 4 : 0);
            }
            if (tid < 3)
                cp4(sb + (SPQ_OFF + 128 + tid) * 4, q_points + (size_t)p0 * 3 + tid, 4);
        }
        cp_commit();
    }
    __syncthreads();

    int buf = 0;
    for (int p = blockIdx.x; p < NQ; p += stride) {
        const int pn = p + stride;
        const bool hn = pn < NQ;

        int iA = 0, iB = 0, iC = 0;
        if (hn) {
            iA = inds[pn * KNB + rowA];
            iB = inds[pn * KNB + 16 + rowA];
            if (tid < 128 && cC < 3) iC = inds[pn * KNB + rowC];
        }

        cp_wait0();
        __syncthreads();     // buffer 'buf' ready

        const int EB = ESM_OFF + buf * 2176;
        const int RB = RSM_OFF + buf * 2176;
        const int SQ = SPQ_OFF + buf * 132;

        // ---- phase 2: inv[f] = 1/sum_k E (interleaved k -> ~2-way conflicts) ----
        {
            int f = tid >> 2, q = tid & 3;
            float s = 0.f;
            #pragma unroll
            for (int j = 0; j < 8; ++j)
                s += sm[EB + (q + 4 * j) * 68 + f];
            s += __shfl_xor_sync(0xffffffffu, s, 1);
            s += __shfl_xor_sync(0xffffffffu, s, 2);
            if (q == 0) sm[INV_OFF + f] = 1.f / s;
        }
        __syncthreads();

        // ---- phase 3: build A'[row][cc] = attn[row,f]*xv[row,i] as half2 ----
        {
            int row = tid >> 3, seg = tid & 7;
            float x0 = sm[SQ + row * 4 + 0] - sm[SQ + 128 + 0];
            float x1 = sm[SQ + row * 4 + 1] - sm[SQ + 128 + 1];
            float x2 = sm[SQ + row * 4 + 2] - sm[SQ + 128 + 2];
            float4 e0 = *(const float4*)(sm + EB + row * 68 + seg * 8);
            float4 e1 = *(const float4*)(sm + EB + row * 68 + seg * 8 + 4);
            float4 i0 = *(const float4*)(sm + INV_OFF + seg * 8);
            float4 i1 = *(const float4*)(sm + INV_OFF + seg * 8 + 4);
            float at[8] = {e0.x*i0.x, e0.y*i0.y, e0.z*i0.z, e0.w*i0.w,
                           e1.x*i1.x, e1.y*i1.y, e1.z*i1.z, e1.w*i1.w};
            float vv[24];
            #pragma unroll
            for (int ff = 0; ff < 8; ++ff) {
                vv[3*ff + 0] = at[ff] * x0;
                vv[3*ff + 1] = at[ff] * x1;
                vv[3*ff + 2] = at[ff] * x2;
            }
            uint32_t* dst = smw + AP_OFF + row * AH_W + seg * 12;
            #pragma unroll
            for (int j = 0; j < 12; ++j)
                dst[j] = pack_h2(vv[2*j], vv[2*j + 1]);
        }
        __syncthreads();

        // ---- prefetch next point into buf^1 (hidden under MMA+epilogue) ----
        if (hn) {
            uint32_t eb = sb + (ESM_OFF + (buf ^ 1) * 2176) * 4;
            uint32_t rb = sb + (RSM_OFF + (buf ^ 1) * 2176) * 4;
            uint32_t sq = sb + (SPQ_OFF + (buf ^ 1) * 132) * 4;
            cp16(eb + (rowA * 68 + f4 * 4) * 4,        g_E + (size_t)iA * FC + f4 * 4);
            cp16(rb + (rowA * 68 + f4 * 4) * 4,        g_R + (size_t)iA * FC + f4 * 4);
            cp16(eb + ((16 + rowA) * 68 + f4 * 4) * 4, g_E + (size_t)iB * FC + f4 * 4);
            cp16(rb + ((16 + rowA) * 68 + f4 * 4) * 4, g_R + (size_t)iB * FC + f4 * 4);
            if (tid < 128 && cC < 3)
                cp4(sq + (rowC * 4 + cC) * 4, s_points + (size_t)iC * 3 + cC,
                    (iC < NQ) ? 4 : 0);
            if (tid < 3)
                cp4(sq + (128 + tid) * 4, q_points + (size_t)pn * 3 + tid, 4);
        }
        cp_commit();

        // ---- phase 4: MMA — warp computes [32 x 192] x [192 x 8] ----
        float d[2][4];
        #pragma unroll
        for (int mt = 0; mt < 2; ++mt)
            #pragma unroll
            for (int j = 0; j < 4; ++j) d[mt][j] = 0.f;
        {
            const uint32_t* AW = smw + AP_OFF;
            #pragma unroll
            for (int kt = 0; kt < 12; ++kt) {
                #pragma unroll
                for (int mt = 0; mt < 2; ++mt) {
                    int base = (mt * 16 + qr) * AH_W + kt * 8 + qc;
                    uint32_t a[4];
                    a[0] = AW[base];
                    a[1] = AW[base + 8 * AH_W];
                    a[2] = AW[base + 4];
                    a[3] = AW[base + 8 * AH_W + 4];
                    mma_f16(d[mt], a, bf[kt]);
                }
            }
        }

        // ---- epilogue: bn1, lrelu, +R, lrelu, k-max (in-warp), store ----
        {
            float mx[2] = {-1e30f, -1e30f};
            #pragma unroll
            for (int mt = 0; mt < 2; ++mt)
                #pragma unroll
                for (int j = 0; j < 4; ++j) {
                    int row = mt * 16 + qr + 8 * (j >> 1);
                    int col = 8 * w + 2 * qc + (j & 1);
                    float ye = d[mt][j];
                    ye = lrelu(ye * sm[S1_OFF + col] + sm[B1_OFF + col]);
                    float y = lrelu(ye + sm[RB + row * 68 + col]);
                    mx[j & 1] = fmaxf(mx[j & 1], y);
                }
            #pragma unroll
            for (int par = 0; par < 2; ++par) {
                float v = mx[par];
                v = fmaxf(v, __shfl_xor_sync(0xffffffffu, v, 4));
                v = fmaxf(v, __shfl_xor_sync(0xffffffffu, v, 8));
                v = fmaxf(v, __shfl_xor_sync(0xffffffffu, v, 16));
                mx[par] = v;
            }
            if (lane < 4) {
                out[p * CO + 8 * w + 2 * lane + 0] = mx[0];
                out[p * CO + 8 * w + 2 * lane + 1] = mx[1];
            }
        }
        // no trailing sync: next loop's cp_wait0+sync orders A'/INV rewrites
        buf ^= 1;
    }
}

extern "C" void kernel_launch(void* const* d_in, const int* in_sizes, int n_in,
                              void* d_out, int out_size)
{
    const float* q    = (const float*)d_in[0];
    const float* s    = (const float*)d_in[1];
    const int*   ind  = (const int*)  d_in[2];
    const float* feat = (const float*)d_in[3];
    const float* Wp2  = (const float*)d_in[4];
    const float* Wat  = (const float*)d_in[5];
    const float* Wre  = (const float*)d_in[6];
    const float* b1g  = (const float*)d_in[15];
    const float* b1b  = (const float*)d_in[16];
    const float* b1m  = (const float*)d_in[17];
    const float* b1v  = (const float*)d_in[18];
    const float* brg  = (const float*)d_in[19];
    const float* brb  = (const float*)d_in[20];
    const float* brm  = (const float*)d_in[21];
    const float* brv  = (const float*)d_in[22];

    int NQ = in_sizes[0] / 3;

    prep_kernel<<<(NQ + 1 + 31) / 32, 256>>>(s, feat, Wp2, Wre,
                                             brg, brb, brm, brv, NQ);

    const int smem_bytes = SMEM_FLOATS * 4;
    cudaFuncSetAttribute(main_kernel, cudaFuncAttributeMaxDynamicSharedMemorySize, smem_bytes);
    int grid = 296;
    if (grid > NQ) grid = NQ;
    main_kernel<<<grid, 256, smem_bytes>>>(ind, s, q, Wat,
                                           b1g, b1b, b1m, b1v,
                                           (float*)d_out, NQ);
}